// round 1
// baseline (speedup 1.0000x reference)
#include <cuda_runtime.h>
#include <math.h>

// ---------------- problem constants ----------------
#define BB 8
#define SS 4096
#define EE 1024
#define SD 8
#define MM (BB*SS)          // 32768
#define LDIN 1032           // E + SD

// ---------------- scratch (device globals, no allocs) ----------------
__device__ float g_Weff[EE * EE];        // W_in[:, :E] @ W_out[:E, :]   (4 MB)
__device__ float g_Wg_eff[EE * SD];      // W_in @ W_g
__device__ float g_bg_eff[SD];
__device__ float g_bout_eff[EE];
__device__ float g_gate[MM * SD];
__device__ float g_si[MM * SD];
__device__ float g_states[MM * SD];

// ---------------- precompute small folded weights ----------------
__global__ void precompute_kernel(const float* __restrict__ W_in,
                                  const float* __restrict__ W_g,
                                  const float* __restrict__ b_g,
                                  const float* __restrict__ b_in,
                                  const float* __restrict__ W_out,
                                  const float* __restrict__ b_out,
                                  float* __restrict__ Wg_eff,
                                  float* __restrict__ bg_eff,
                                  float* __restrict__ bout_eff)
{
    int gid = blockIdx.x * blockDim.x + threadIdx.x;
    if (gid < EE * SD) {
        int e = gid >> 3, d = gid & 7;
        float s = 0.f;
        const float* wr = W_in + (size_t)e * LDIN;
        #pragma unroll 4
        for (int c = 0; c < LDIN; c++) s = fmaf(wr[c], W_g[c * SD + d], s);
        Wg_eff[e * SD + d] = s;
    } else if (gid < EE * SD + SD) {
        int d = gid - EE * SD;
        float s = b_g[d];
        for (int c = 0; c < LDIN; c++) s = fmaf(b_in[c], W_g[c * SD + d], s);
        bg_eff[d] = s;
    } else if (gid < EE * SD + SD + EE) {
        int n = gid - (EE * SD + SD);
        float s = b_out[n];
        for (int c = 0; c < EE; c++) s = fmaf(b_in[c], W_out[(size_t)c * EE + n], s);
        bout_eff[n] = s;
    }
}

// ---------------- tiled fp32 SGEMM: C = A(MxK, lda) * B(KxN, ldb) [+ epilogue] ----
// 128x128 block tile, BK=8, 256 threads, 8x8 per thread.
// Optional epilogue: C += Srank(Mx8) * Wbot(8xN, ld=ldc) + bias(N)
#define BM 128
#define BN 128
#define BK 8

__global__ __launch_bounds__(256, 2)
void sgemm_kernel(const float* __restrict__ A, int lda,
                  const float* __restrict__ B, int ldb,
                  float* __restrict__ C, int ldc,
                  int K,
                  const float* __restrict__ bias,     // or null
                  const float* __restrict__ Srank,    // [M,8] or null
                  const float* __restrict__ Wbot)     // [8, N] ld ldc, or null
{
    __shared__ float As[BK][BM];
    __shared__ float Bs[BK][BN];
    __shared__ float sWb[SD][BN];
    __shared__ float sSt[BM * SD];
    __shared__ float sBias[BN];

    const int tid = threadIdx.x;
    const int tx = tid & 15;          // 0..15 -> n
    const int ty = tid >> 4;          // 0..15 -> m
    const int bn0 = blockIdx.x * BN;
    const int bm0 = blockIdx.y * BM;

    // epilogue data loads (consumed only after many syncthreads)
    if (Wbot != nullptr) {
        // 8 x 128 W rows
        for (int idx = tid; idx < SD * BN; idx += 256) {
            int d = idx >> 7, nl = idx & 127;
            sWb[d][nl] = Wbot[(size_t)d * ldc + bn0 + nl];
        }
        // 128 rows x 8 states -> 1024 floats, float4 per thread
        *((float4*)&sSt[tid * 4]) = *((const float4*)&Srank[(size_t)bm0 * SD + tid * 4]);
        if (tid < BN) sBias[tid] = bias[bn0 + tid];
    }

    const int rowA  = tid >> 1;          // 0..127
    const int colA4 = (tid & 1) * 4;     // 0 or 4
    const int rowB  = tid >> 5;          // 0..7
    const int colB4 = (tid & 31) * 4;

    const float* Aptr = A + (size_t)(bm0 + rowA) * lda + colA4;
    const float* Bptr = B + (size_t)rowB * ldb + bn0 + colB4;

    float acc[8][8];
    #pragma unroll
    for (int i = 0; i < 8; i++)
        #pragma unroll
        for (int j = 0; j < 8; j++) acc[i][j] = 0.f;

    for (int k0 = 0; k0 < K; k0 += BK) {
        float4 a4 = *((const float4*)Aptr);
        float4 b4 = *((const float4*)Bptr);
        As[colA4 + 0][rowA] = a4.x;
        As[colA4 + 1][rowA] = a4.y;
        As[colA4 + 2][rowA] = a4.z;
        As[colA4 + 3][rowA] = a4.w;
        *((float4*)&Bs[rowB][colB4]) = b4;
        __syncthreads();

        #pragma unroll
        for (int k = 0; k < BK; k++) {
            float4 ra0 = *((const float4*)&As[k][ty * 8]);
            float4 ra1 = *((const float4*)&As[k][ty * 8 + 4]);
            float4 rb0 = *((const float4*)&Bs[k][tx * 8]);
            float4 rb1 = *((const float4*)&Bs[k][tx * 8 + 4]);
            float ra[8] = {ra0.x, ra0.y, ra0.z, ra0.w, ra1.x, ra1.y, ra1.z, ra1.w};
            float rb[8] = {rb0.x, rb0.y, rb0.z, rb0.w, rb1.x, rb1.y, rb1.z, rb1.w};
            #pragma unroll
            for (int i = 0; i < 8; i++)
                #pragma unroll
                for (int j = 0; j < 8; j++)
                    acc[i][j] = fmaf(ra[i], rb[j], acc[i][j]);
        }
        __syncthreads();
        Aptr += BK;
        Bptr += (size_t)BK * ldb;
    }

    // epilogue + store
    #pragma unroll
    for (int i = 0; i < 8; i++) {
        int ml = ty * 8 + i;
        size_t crow = (size_t)(bm0 + ml) * ldc + bn0;
        float v[8];
        #pragma unroll
        for (int j = 0; j < 8; j++) v[j] = acc[i][j];
        if (Wbot != nullptr) {
            #pragma unroll
            for (int j = 0; j < 8; j++) {
                int nl = tx * 8 + j;
                float s = v[j] + sBias[nl];
                #pragma unroll
                for (int d = 0; d < SD; d++)
                    s = fmaf(sSt[ml * SD + d], sWb[d][nl], s);
                v[j] = s;
            }
        }
        float4 o0 = {v[0], v[1], v[2], v[3]};
        float4 o1 = {v[4], v[5], v[6], v[7]};
        *((float4*)&C[crow + tx * 8])     = o0;
        *((float4*)&C[crow + tx * 8 + 4]) = o1;
    }
}

// ---------------- skinny pass: gate + state_in (N=16 over K=1024) ----------------
// warp per group of 4 rows; weights staged in smem transposed [16][512] per phase.
__global__ __launch_bounds__(256)
void gate_si_kernel(const float* __restrict__ x,
                    const float* __restrict__ Wg_eff,   // [E][8]
                    const float* __restrict__ W_in,     // for si columns
                    const float* __restrict__ bg_eff,   // [8]
                    const float* __restrict__ b_in,     // [1032]
                    float* __restrict__ gate,
                    float* __restrict__ si)
{
    __shared__ float sWT[16][512];
    const int tid = threadIdx.x;
    const int lane = tid & 31;
    const int warp = tid >> 5;           // 0..7
    const int m0 = blockIdx.x * 32 + warp * 4;

    float acc[4][16];
    #pragma unroll
    for (int r = 0; r < 4; r++)
        #pragma unroll
        for (int d = 0; d < 16; d++) acc[r][d] = 0.f;

    for (int p = 0; p < 2; p++) {
        for (int idx = tid; idx < 16 * 512; idx += 256) {
            int d = idx >> 9, el = idx & 511;
            int e = p * 512 + el;
            sWT[d][el] = (d < 8) ? Wg_eff[e * SD + d]
                                 : W_in[(size_t)e * LDIN + EE + (d - 8)];
        }
        __syncthreads();

        for (int eb = 0; eb < 512; eb += 32) {
            float xv[4];
            #pragma unroll
            for (int r = 0; r < 4; r++)
                xv[r] = x[(size_t)(m0 + r) * EE + p * 512 + eb + lane];
            #pragma unroll
            for (int d = 0; d < 16; d++) {
                float w = sWT[d][eb + lane];
                #pragma unroll
                for (int r = 0; r < 4; r++)
                    acc[r][d] = fmaf(xv[r], w, acc[r][d]);
            }
        }
        __syncthreads();
    }

    // reduce across 32 lanes (each lane held e = lane mod 32)
    #pragma unroll
    for (int r = 0; r < 4; r++) {
        #pragma unroll
        for (int d = 0; d < 16; d++) {
            float v = acc[r][d];
            v += __shfl_xor_sync(0xffffffffu, v, 16);
            v += __shfl_xor_sync(0xffffffffu, v, 8);
            v += __shfl_xor_sync(0xffffffffu, v, 4);
            v += __shfl_xor_sync(0xffffffffu, v, 2);
            v += __shfl_xor_sync(0xffffffffu, v, 1);
            acc[r][d] = v;
        }
        int m = m0 + r;
        if (lane < 8) {
            float logit = acc[r][lane] + bg_eff[lane];
            gate[m * SD + lane] = 1.0f / (1.0f + expf(-logit));
        } else if (lane < 16) {
            si[m * SD + (lane - 8)] = acc[r][lane] + b_in[EE + (lane - 8)];
        }
    }
}

// ---------------- sequential scan: 64 independent chains ----------------
__global__ void scan_kernel(const float* __restrict__ gate,
                            const float* __restrict__ si,
                            float* __restrict__ states,
                            float* __restrict__ final_state)
{
    int t = threadIdx.x;            // 0..63
    int b = t >> 3, d = t & 7;
    const float* gp = gate + (size_t)b * SS * SD + d;
    const float* sp = si   + (size_t)b * SS * SD + d;
    float*       op = states + (size_t)b * SS * SD + d;

    float st = 0.f;
    for (int s = 0; s < SS; s += 16) {
        float g[16], c[16];
        #pragma unroll
        for (int u = 0; u < 16; u++) {
            g[u] = gp[(s + u) * SD];
            float sv = sp[(s + u) * SD];
            c[u] = sv - g[u] * sv;      // (1-g)*si off the dependent chain
        }
        #pragma unroll
        for (int u = 0; u < 16; u++) {
            st = fmaf(g[u], st, c[u]);  // single FMA on the chain
            op[(s + u) * SD] = st;
        }
    }
    final_state[b * SD + d] = st;
}

// ---------------- launch ----------------
extern "C" void kernel_launch(void* const* d_in, const int* in_sizes, int n_in,
                              void* d_out, int out_size)
{
    const float* x     = (const float*)d_in[0];
    const float* W_in  = (const float*)d_in[1];
    const float* b_in  = (const float*)d_in[2];
    const float* W_g   = (const float*)d_in[3];
    const float* b_g   = (const float*)d_in[4];
    const float* W_out = (const float*)d_in[5];
    const float* b_out = (const float*)d_in[6];
    float* out = (float*)d_out;

    float *Weff, *Wg_eff, *bg_eff, *bout_eff, *gate, *si, *states;
    cudaGetSymbolAddress((void**)&Weff,     g_Weff);
    cudaGetSymbolAddress((void**)&Wg_eff,   g_Wg_eff);
    cudaGetSymbolAddress((void**)&bg_eff,   g_bg_eff);
    cudaGetSymbolAddress((void**)&bout_eff, g_bout_eff);
    cudaGetSymbolAddress((void**)&gate,     g_gate);
    cudaGetSymbolAddress((void**)&si,       g_si);
    cudaGetSymbolAddress((void**)&states,   g_states);

    // 1) small folded weights
    int tot = EE * SD + SD + EE;
    precompute_kernel<<<(tot + 255) / 256, 256>>>(W_in, W_g, b_g, b_in, W_out, b_out,
                                                  Wg_eff, bg_eff, bout_eff);

    // 2) W_eff = W_in[:, :E] @ W_out[:E, :]   (1024x1024x1024)
    sgemm_kernel<<<dim3(EE / BN, EE / BM), 256>>>(W_in, LDIN, W_out, EE,
                                                  Weff, EE, EE,
                                                  nullptr, nullptr, nullptr);

    // 3) gate + state_in directly from x (skinny N=16)
    gate_si_kernel<<<MM / 32, 256>>>(x, Wg_eff, W_in, bg_eff, b_in, gate, si);

    // 4) sequential scan (also writes final_state at tail of output)
    scan_kernel<<<1, 64>>>(gate, si, states, out + (size_t)MM * EE);

    // 5) out = x @ W_eff + states @ W_out[E:, :] + bout_eff
    sgemm_kernel<<<dim3(EE / BN, MM / BM), 256>>>(x, EE, Weff, EE,
                                                  out, EE, EE,
                                                  bout_eff, states,
                                                  W_out + (size_t)EE * EE);
}

// round 2
// speedup vs baseline: 1.0036x; 1.0036x over previous
#include <cuda_runtime.h>
#include <math.h>

// ---------------- problem constants ----------------
#define BB 8
#define SS 4096
#define EE 1024
#define SD 8
#define MM (BB*SS)          // 32768
#define LDIN 1032           // E + SD

// ---------------- scratch (device globals, no allocs) ----------------
__device__ float g_Weff[EE * EE];        // W_in[:, :E] @ W_out[:E, :]   (4 MB)
__device__ float g_Wg_eff[EE * SD];      // W_in @ W_g
__device__ float g_bg_eff[SD];
__device__ float g_bout_eff[EE];
__device__ float g_gate[MM * SD];
__device__ float g_si[MM * SD];
__device__ float g_states[MM * SD];

// ---------------- precompute small folded weights ----------------
__global__ void precompute_kernel(const float* __restrict__ W_in,
                                  const float* __restrict__ W_g,
                                  const float* __restrict__ b_g,
                                  const float* __restrict__ b_in,
                                  const float* __restrict__ W_out,
                                  const float* __restrict__ b_out,
                                  float* __restrict__ Wg_eff,
                                  float* __restrict__ bg_eff,
                                  float* __restrict__ bout_eff)
{
    int gid = blockIdx.x * blockDim.x + threadIdx.x;
    if (gid < EE * SD) {
        int e = gid >> 3, d = gid & 7;
        float s = 0.f;
        const float* wr = W_in + (size_t)e * LDIN;
        #pragma unroll 4
        for (int c = 0; c < LDIN; c++) s = fmaf(wr[c], W_g[c * SD + d], s);
        Wg_eff[e * SD + d] = s;
    } else if (gid < EE * SD + SD) {
        int d = gid - EE * SD;
        float s = b_g[d];
        for (int c = 0; c < LDIN; c++) s = fmaf(b_in[c], W_g[c * SD + d], s);
        bg_eff[d] = s;
    } else if (gid < EE * SD + SD + EE) {
        int n = gid - (EE * SD + SD);
        float s = b_out[n];
        for (int c = 0; c < EE; c++) s = fmaf(b_in[c], W_out[(size_t)c * EE + n], s);
        bout_eff[n] = s;
    }
}

// ---------------- tiled fp32 SGEMM: C = A(MxK, lda) * B(KxN, ldb) [+ epilogue] ----
// 128x128 block tile, BK=8, 256 threads, 8x8 per thread.
// Optional epilogue: C += Srank(Mx8) * Wbot(8xN, ld=ldc) + bias(N)
#define BM 128
#define BN 128
#define BK 8

__global__ __launch_bounds__(256, 2)
void sgemm_kernel(const float* __restrict__ A, int lda,
                  const float* __restrict__ B, int ldb,
                  float* __restrict__ C, int ldc,
                  int K,
                  const float* __restrict__ bias,     // or null
                  const float* __restrict__ Srank,    // [M,8] or null
                  const float* __restrict__ Wbot)     // [8, N] ld ldc, or null
{
    __shared__ float As[BK][BM];
    __shared__ float Bs[BK][BN];
    __shared__ float sWb[SD][BN];
    __shared__ float sSt[BM * SD];
    __shared__ float sBias[BN];

    const int tid = threadIdx.x;
    const int tx = tid & 15;          // 0..15 -> n
    const int ty = tid >> 4;          // 0..15 -> m
    const int bn0 = blockIdx.x * BN;
    const int bm0 = blockIdx.y * BM;

    // epilogue data loads (consumed only after many syncthreads)
    if (Wbot != nullptr) {
        // 8 x 128 W rows
        for (int idx = tid; idx < SD * BN; idx += 256) {
            int d = idx >> 7, nl = idx & 127;
            sWb[d][nl] = Wbot[(size_t)d * ldc + bn0 + nl];
        }
        // 128 rows x 8 states -> 1024 floats, float4 per thread
        *((float4*)&sSt[tid * 4]) = *((const float4*)&Srank[(size_t)bm0 * SD + tid * 4]);
        if (tid < BN) sBias[tid] = bias[bn0 + tid];
    }

    const int rowA  = tid >> 1;          // 0..127
    const int colA4 = (tid & 1) * 4;     // 0 or 4
    const int rowB  = tid >> 5;          // 0..7
    const int colB4 = (tid & 31) * 4;

    const float* Aptr = A + (size_t)(bm0 + rowA) * lda + colA4;
    const float* Bptr = B + (size_t)rowB * ldb + bn0 + colB4;

    float acc[8][8];
    #pragma unroll
    for (int i = 0; i < 8; i++)
        #pragma unroll
        for (int j = 0; j < 8; j++) acc[i][j] = 0.f;

    for (int k0 = 0; k0 < K; k0 += BK) {
        float4 a4 = *((const float4*)Aptr);
        float4 b4 = *((const float4*)Bptr);
        As[colA4 + 0][rowA] = a4.x;
        As[colA4 + 1][rowA] = a4.y;
        As[colA4 + 2][rowA] = a4.z;
        As[colA4 + 3][rowA] = a4.w;
        *((float4*)&Bs[rowB][colB4]) = b4;
        __syncthreads();

        #pragma unroll
        for (int k = 0; k < BK; k++) {
            float4 ra0 = *((const float4*)&As[k][ty * 8]);
            float4 ra1 = *((const float4*)&As[k][ty * 8 + 4]);
            float4 rb0 = *((const float4*)&Bs[k][tx * 8]);
            float4 rb1 = *((const float4*)&Bs[k][tx * 8 + 4]);
            float ra[8] = {ra0.x, ra0.y, ra0.z, ra0.w, ra1.x, ra1.y, ra1.z, ra1.w};
            float rb[8] = {rb0.x, rb0.y, rb0.z, rb0.w, rb1.x, rb1.y, rb1.z, rb1.w};
            #pragma unroll
            for (int i = 0; i < 8; i++)
                #pragma unroll
                for (int j = 0; j < 8; j++)
                    acc[i][j] = fmaf(ra[i], rb[j], acc[i][j]);
        }
        __syncthreads();
        Aptr += BK;
        Bptr += (size_t)BK * ldb;
    }

    // epilogue + store
    #pragma unroll
    for (int i = 0; i < 8; i++) {
        int ml = ty * 8 + i;
        size_t crow = (size_t)(bm0 + ml) * ldc + bn0;
        float v[8];
        #pragma unroll
        for (int j = 0; j < 8; j++) v[j] = acc[i][j];
        if (Wbot != nullptr) {
            #pragma unroll
            for (int j = 0; j < 8; j++) {
                int nl = tx * 8 + j;
                float s = v[j] + sBias[nl];
                #pragma unroll
                for (int d = 0; d < SD; d++)
                    s = fmaf(sSt[ml * SD + d], sWb[d][nl], s);
                v[j] = s;
            }
        }
        float4 o0 = {v[0], v[1], v[2], v[3]};
        float4 o1 = {v[4], v[5], v[6], v[7]};
        *((float4*)&C[crow + tx * 8])     = o0;
        *((float4*)&C[crow + tx * 8 + 4]) = o1;
    }
}

// ---------------- skinny pass: gate + state_in (N=16 over K=1024) ----------------
// warp per group of 4 rows; weights staged in smem transposed [16][512] per phase.
__global__ __launch_bounds__(256)
void gate_si_kernel(const float* __restrict__ x,
                    const float* __restrict__ Wg_eff,   // [E][8]
                    const float* __restrict__ W_in,     // for si columns
                    const float* __restrict__ bg_eff,   // [8]
                    const float* __restrict__ b_in,     // [1032]
                    float* __restrict__ gate,
                    float* __restrict__ si)
{
    __shared__ float sWT[16][512];
    const int tid = threadIdx.x;
    const int lane = tid & 31;
    const int warp = tid >> 5;           // 0..7
    const int m0 = blockIdx.x * 32 + warp * 4;

    float acc[4][16];
    #pragma unroll
    for (int r = 0; r < 4; r++)
        #pragma unroll
        for (int d = 0; d < 16; d++) acc[r][d] = 0.f;

    for (int p = 0; p < 2; p++) {
        for (int idx = tid; idx < 16 * 512; idx += 256) {
            int d = idx >> 9, el = idx & 511;
            int e = p * 512 + el;
            sWT[d][el] = (d < 8) ? Wg_eff[e * SD + d]
                                 : W_in[(size_t)e * LDIN + EE + (d - 8)];
        }
        __syncthreads();

        for (int eb = 0; eb < 512; eb += 32) {
            float xv[4];
            #pragma unroll
            for (int r = 0; r < 4; r++)
                xv[r] = x[(size_t)(m0 + r) * EE + p * 512 + eb + lane];
            #pragma unroll
            for (int d = 0; d < 16; d++) {
                float w = sWT[d][eb + lane];
                #pragma unroll
                for (int r = 0; r < 4; r++)
                    acc[r][d] = fmaf(xv[r], w, acc[r][d]);
            }
        }
        __syncthreads();
    }

    // reduce across 32 lanes (each lane held e = lane mod 32)
    #pragma unroll
    for (int r = 0; r < 4; r++) {
        #pragma unroll
        for (int d = 0; d < 16; d++) {
            float v = acc[r][d];
            v += __shfl_xor_sync(0xffffffffu, v, 16);
            v += __shfl_xor_sync(0xffffffffu, v, 8);
            v += __shfl_xor_sync(0xffffffffu, v, 4);
            v += __shfl_xor_sync(0xffffffffu, v, 2);
            v += __shfl_xor_sync(0xffffffffu, v, 1);
            acc[r][d] = v;
        }
        int m = m0 + r;
        if (lane < 8) {
            float logit = acc[r][lane] + bg_eff[lane];
            gate[m * SD + lane] = 1.0f / (1.0f + expf(-logit));
        } else if (lane < 16) {
            si[m * SD + (lane - 8)] = acc[r][lane] + b_in[EE + (lane - 8)];
        }
    }
}

// ---------------- sequential scan: 64 independent chains ----------------
__global__ void scan_kernel(const float* __restrict__ gate,
                            const float* __restrict__ si,
                            float* __restrict__ states,
                            float* __restrict__ final_state)
{
    int t = threadIdx.x;            // 0..63
    int b = t >> 3, d = t & 7;
    const float* gp = gate + (size_t)b * SS * SD + d;
    const float* sp = si   + (size_t)b * SS * SD + d;
    float*       op = states + (size_t)b * SS * SD + d;

    float st = 0.f;
    for (int s = 0; s < SS; s += 16) {
        float g[16], c[16];
        #pragma unroll
        for (int u = 0; u < 16; u++) {
            g[u] = gp[(s + u) * SD];
            float sv = sp[(s + u) * SD];
            c[u] = sv - g[u] * sv;      // (1-g)*si off the dependent chain
        }
        #pragma unroll
        for (int u = 0; u < 16; u++) {
            st = fmaf(g[u], st, c[u]);  // single FMA on the chain
            op[(s + u) * SD] = st;
        }
    }
    final_state[b * SD + d] = st;
}

// ---------------- launch ----------------
extern "C" void kernel_launch(void* const* d_in, const int* in_sizes, int n_in,
                              void* d_out, int out_size)
{
    const float* x     = (const float*)d_in[0];
    const float* W_in  = (const float*)d_in[1];
    const float* b_in  = (const float*)d_in[2];
    const float* W_g   = (const float*)d_in[3];
    const float* b_g   = (const float*)d_in[4];
    const float* W_out = (const float*)d_in[5];
    const float* b_out = (const float*)d_in[6];
    float* out = (float*)d_out;

    float *Weff, *Wg_eff, *bg_eff, *bout_eff, *gate, *si, *states;
    cudaGetSymbolAddress((void**)&Weff,     g_Weff);
    cudaGetSymbolAddress((void**)&Wg_eff,   g_Wg_eff);
    cudaGetSymbolAddress((void**)&bg_eff,   g_bg_eff);
    cudaGetSymbolAddress((void**)&bout_eff, g_bout_eff);
    cudaGetSymbolAddress((void**)&gate,     g_gate);
    cudaGetSymbolAddress((void**)&si,       g_si);
    cudaGetSymbolAddress((void**)&states,   g_states);

    // 1) small folded weights
    int tot = EE * SD + SD + EE;
    precompute_kernel<<<(tot + 255) / 256, 256>>>(W_in, W_g, b_g, b_in, W_out, b_out,
                                                  Wg_eff, bg_eff, bout_eff);

    // 2) W_eff = W_in[:, :E] @ W_out[:E, :]   (1024x1024x1024)
    sgemm_kernel<<<dim3(EE / BN, EE / BM), 256>>>(W_in, LDIN, W_out, EE,
                                                  Weff, EE, EE,
                                                  nullptr, nullptr, nullptr);

    // 3) gate + state_in directly from x (skinny N=16)
    gate_si_kernel<<<MM / 32, 256>>>(x, Wg_eff, W_in, bg_eff, b_in, gate, si);

    // 4) sequential scan (also writes final_state at tail of output)
    scan_kernel<<<1, 64>>>(gate, si, states, out + (size_t)MM * EE);

    // 5) out = x @ W_eff + states @ W_out[E:, :] + bout_eff
    sgemm_kernel<<<dim3(EE / BN, MM / BM), 256>>>(x, EE, Weff, EE,
                                                  out, EE, EE,
                                                  bout_eff, states,
                                                  W_out + (size_t)EE * EE);
}